// round 1
// baseline (speedup 1.0000x reference)
#include <cuda_runtime.h>
#include <math.h>

#define TOK 2048
#define DM  768
#define HN  12
#define HD  64
#define SQ  512
#define BB  4
#define LL  4
#define EE  8
#define FF  3072
#define VV  32000

// ---------------- scratch (device globals; no runtime allocation) ----------------
__device__ float g_emb[TOK * DM];
__device__ float g_x[TOK * DM];
__device__ float g_qkv[TOK * 3 * DM];
__device__ float g_att[BB * HN * SQ * SQ];      // 50.3 MB
__device__ float g_o[TOK * DM];
__device__ float g_o2[TOK * DM];
__device__ float g_h[TOK * FF];                 // 25.2 MB
__device__ float g_moe[TOK * DM];
__device__ float g_gates[TOK * EE];

// ---------------- reductions ----------------
__device__ __forceinline__ float warp_sum(float v) {
    #pragma unroll
    for (int o = 16; o; o >>= 1) v += __shfl_xor_sync(0xffffffffu, v, o);
    return v;
}
__device__ __forceinline__ float warp_max(float v) {
    #pragma unroll
    for (int o = 16; o; o >>= 1) v = fmaxf(v, __shfl_xor_sync(0xffffffffu, v, o));
    return v;
}

// ---------------- generic NT GEMM with fused epilogues ----------------
// C[M,N] = epi(A[M,K] @ W[N,K]^T)
enum { EPI_BIAS = 0, EPI_QEMB, EPI_POS, EPI_ENT, EPI_GELU, EPI_MOE };

struct GemmP {
    const float* A; const float* W; const float* bias; float* C;
    int M, N, K;
    const float* r0; const float* r1;
    const float* scal;      // device scalar (quantum_state)
    const float* gate;      // per-row gate, stride EE
    float alpha;
    int accum;
};

template <int EPI>
__global__ void __launch_bounds__(256) gemm_nt(GemmP p) {
    __shared__ float As[8][128];
    __shared__ float Bs[8][128];
    const int tid = threadIdx.x;
    const int m0 = blockIdx.y * 128, n0 = blockIdx.x * 128;
    const int ty = tid >> 4, tx = tid & 15;
    const int lrow = tid >> 1, lc4 = (tid & 1) * 4;

    const float* Ag = p.A + (size_t)(m0 + lrow) * p.K + lc4;
    const float* Wg = p.W + (size_t)(n0 + lrow) * p.K + lc4;

    float acc[8][8];
    #pragma unroll
    for (int i = 0; i < 8; i++)
        #pragma unroll
        for (int j = 0; j < 8; j++) acc[i][j] = 0.f;

    for (int k0 = 0; k0 < p.K; k0 += 8) {
        float4 a4 = *(const float4*)(Ag + k0);
        float4 b4 = *(const float4*)(Wg + k0);
        As[lc4 + 0][lrow] = a4.x; As[lc4 + 1][lrow] = a4.y;
        As[lc4 + 2][lrow] = a4.z; As[lc4 + 3][lrow] = a4.w;
        Bs[lc4 + 0][lrow] = b4.x; Bs[lc4 + 1][lrow] = b4.y;
        Bs[lc4 + 2][lrow] = b4.z; Bs[lc4 + 3][lrow] = b4.w;
        __syncthreads();
        #pragma unroll
        for (int k = 0; k < 8; k++) {
            float4 ra0 = *(const float4*)&As[k][ty * 8];
            float4 ra1 = *(const float4*)&As[k][ty * 8 + 4];
            float4 rb0 = *(const float4*)&Bs[k][tx * 8];
            float4 rb1 = *(const float4*)&Bs[k][tx * 8 + 4];
            float ra[8] = {ra0.x, ra0.y, ra0.z, ra0.w, ra1.x, ra1.y, ra1.z, ra1.w};
            float rb[8] = {rb0.x, rb0.y, rb0.z, rb0.w, rb1.x, rb1.y, rb1.z, rb1.w};
            #pragma unroll
            for (int i = 0; i < 8; i++)
                #pragma unroll
                for (int j = 0; j < 8; j++)
                    acc[i][j] = fmaf(ra[i], rb[j], acc[i][j]);
        }
        __syncthreads();
    }

    const float qsv = (EPI == EPI_QEMB) ? *p.scal : 0.f;
    #pragma unroll
    for (int i = 0; i < 8; i++) {
        const int m = m0 + ty * 8 + i;
        const size_t cr = (size_t)m * p.N;
        const float gv = (EPI == EPI_MOE) ? p.gate[(size_t)m * EE] : 0.f;
        #pragma unroll
        for (int j = 0; j < 8; j++) {
            const int n = n0 + tx * 8 + j;
            const float a = acc[i][j];
            float out;
            if (EPI == EPI_BIAS) {
                out = a + p.bias[n];
            } else if (EPI == EPI_QEMB) {
                out = p.r0[cr + n] * (1.f - qsv) + (a + p.bias[n]) * qsv;
            } else if (EPI == EPI_POS) {
                out = p.r0[cr + n] + p.alpha * a + p.bias[n];
            } else if (EPI == EPI_ENT) {
                out = p.r0[cr + n] + p.r1[cr + n] + 0.1f * (a + p.bias[n]);
            } else if (EPI == EPI_GELU) {
                float t = a + p.bias[n];
                out = 0.5f * t * (1.f + erff(t * 0.70710678118654752f));
            } else { // EPI_MOE
                out = gv * (a + p.bias[n]);
                if (p.accum) out += p.C[cr + n];
            }
            p.C[cr + n] = out;
        }
    }
}

// ---------------- embedding gather ----------------
__global__ void __launch_bounds__(256) gather_emb(const int* __restrict__ src,
                                                  const float* __restrict__ embW,
                                                  float* __restrict__ emb) {
    const int t = blockIdx.x;
    const int id = src[t];
    const float* s = embW + (size_t)id * DM;
    float* d = emb + (size_t)t * DM;
    for (int i = threadIdx.x; i < DM; i += 256) d[i] = s[i];
}

// ---------------- attention: scores = Q K^T * scale ----------------
__global__ void __launch_bounds__(256) attn_scores(const float* __restrict__ qkv,
                                                   float* __restrict__ att, float scale) {
    __shared__ float Qs[32][65];
    __shared__ float Ks[64][65];
    const int z = blockIdx.y;
    const int b = z / HN, h = z % HN;
    const int q0 = blockIdx.x * 32;
    const int tid = threadIdx.x;
    const float* qb = qkv + (size_t)(b * SQ) * (3 * DM) + h * HD;

    for (int i = tid; i < 32 * 64; i += 256) {
        int r = i >> 6, d = i & 63;
        Qs[r][d] = qb[(size_t)(q0 + r) * (3 * DM) + d];
    }
    const int row = tid >> 3, c0 = (tid & 7) * 8;
    float* attb = att + ((size_t)z * SQ + q0) * SQ;

    for (int kt = 0; kt < SQ; kt += 64) {
        __syncthreads();
        for (int i = tid; i < 64 * 64; i += 256) {
            int r = i >> 6, d = i & 63;
            Ks[r][d] = qb[(size_t)(kt + r) * (3 * DM) + DM + d];
        }
        __syncthreads();
        float acc[8] = {0, 0, 0, 0, 0, 0, 0, 0};
        #pragma unroll 8
        for (int d = 0; d < 64; d++) {
            float qv = Qs[row][d];
            #pragma unroll
            for (int j = 0; j < 8; j++) acc[j] = fmaf(qv, Ks[c0 + j][d], acc[j]);
        }
        #pragma unroll
        for (int j = 0; j < 8; j++)
            attb[(size_t)row * SQ + kt + c0 + j] = acc[j] * scale;
    }
}

// ---------------- softmax over rows of 512 ----------------
__global__ void __launch_bounds__(256) softmax512(float* __restrict__ att) {
    __shared__ float red[9];
    float* p = att + (size_t)blockIdx.x * SQ;
    const int tid = threadIdx.x, lane = tid & 31, w = tid >> 5;
    float v0 = p[tid], v1 = p[tid + 256];
    float m = warp_max(fmaxf(v0, v1));
    if (lane == 0) red[w] = m;
    __syncthreads();
    if (tid == 0) {
        float mm = red[0];
        for (int i = 1; i < 8; i++) mm = fmaxf(mm, red[i]);
        red[8] = mm;
    }
    __syncthreads();
    m = red[8];
    float e0 = expf(v0 - m), e1 = expf(v1 - m);
    float s = warp_sum(e0 + e1);
    __syncthreads();
    if (lane == 0) red[w] = s;
    __syncthreads();
    if (tid == 0) {
        float t = 0;
        for (int i = 0; i < 8; i++) t += red[i];
        red[8] = 1.f / t;
    }
    __syncthreads();
    const float inv = red[8];
    p[tid] = e0 * inv;
    p[tid + 256] = e1 * inv;
}

// ---------------- attention: O = att @ V ----------------
__global__ void __launch_bounds__(256) attn_av(const float* __restrict__ qkv,
                                               const float* __restrict__ att,
                                               float* __restrict__ o) {
    __shared__ float Ps[32][65];
    __shared__ float Vs[64][65];
    const int z = blockIdx.y;
    const int b = z / HN, h = z % HN;
    const int q0 = blockIdx.x * 32;
    const int tid = threadIdx.x;
    const float* vb = qkv + (size_t)(b * SQ) * (3 * DM) + 2 * DM + h * HD;
    const float* attb = att + ((size_t)z * SQ + q0) * SQ;
    const int row = tid >> 3, c0 = (tid & 7) * 8;
    float acc[8] = {0, 0, 0, 0, 0, 0, 0, 0};

    for (int kt = 0; kt < SQ; kt += 64) {
        __syncthreads();
        for (int i = tid; i < 32 * 64; i += 256) {
            int r = i >> 6, d = i & 63;
            Ps[r][d] = attb[(size_t)r * SQ + kt + d];
        }
        for (int i = tid; i < 64 * 64; i += 256) {
            int r = i >> 6, d = i & 63;
            Vs[r][d] = vb[(size_t)(kt + r) * (3 * DM) + d];
        }
        __syncthreads();
        #pragma unroll 8
        for (int kk = 0; kk < 64; kk++) {
            float a = Ps[row][kk];
            #pragma unroll
            for (int j = 0; j < 8; j++) acc[j] = fmaf(a, Vs[kk][c0 + j], acc[j]);
        }
    }
    float* ob = o + (size_t)(b * SQ + q0 + row) * DM + h * HD + c0;
    #pragma unroll
    for (int j = 0; j < 8; j++) ob[j] = acc[j];
}

// ---------------- gates: softmax(x gw^T+gb) * (1+0.1*sigmoid(x qw^T+qb)), renormalized ----------------
__global__ void __launch_bounds__(256) gate_kernel(const float* __restrict__ x,
                                                   const float* __restrict__ gw, const float* __restrict__ gb,
                                                   const float* __restrict__ qw, const float* __restrict__ qb,
                                                   float* __restrict__ gates) {
    __shared__ float xs[DM];
    __shared__ float sg[EE], sq[EE];
    const int t = blockIdx.x, tid = threadIdx.x;
    const int w = tid >> 5, lane = tid & 31;
    for (int d = tid; d < DM; d += 256) xs[d] = x[(size_t)t * DM + d];
    __syncthreads();
    const float* g1 = gw + (size_t)w * DM;
    const float* g2 = qw + (size_t)w * DM;
    float s1 = 0.f, s2 = 0.f;
    for (int d = lane; d < DM; d += 32) {
        float xv = xs[d];
        s1 = fmaf(xv, g1[d], s1);
        s2 = fmaf(xv, g2[d], s2);
    }
    s1 = warp_sum(s1); s2 = warp_sum(s2);
    if (lane == 0) { sg[w] = s1 + gb[w]; sq[w] = s2 + qb[w]; }
    __syncthreads();
    if (tid == 0) {
        float mx = sg[0];
        for (int e = 1; e < EE; e++) mx = fmaxf(mx, sg[e]);
        float ge[EE], s = 0.f;
        for (int e = 0; e < EE; e++) { ge[e] = expf(sg[e] - mx); s += ge[e]; }
        float inv = 1.f / s, tot = 0.f;
        for (int e = 0; e < EE; e++) {
            float qg = 1.f / (1.f + expf(-sq[e]));
            ge[e] = ge[e] * inv * (1.f + 0.1f * qg);
            tot += ge[e];
        }
        float invt = 1.f / tot;
        for (int e = 0; e < EE; e++) gates[(size_t)t * EE + e] = ge[e] * invt;
    }
}

// ---------------- x = LN(x + moe) ----------------
__global__ void __launch_bounds__(256) ln_add(float* __restrict__ x, const float* __restrict__ moe,
                                              const float* __restrict__ g, const float* __restrict__ b) {
    __shared__ float ys[DM];
    __shared__ float red[9];
    const int t = blockIdx.x, tid = threadIdx.x;
    const int lane = tid & 31, w = tid >> 5;
    const size_t base = (size_t)t * DM;
    float s = 0.f;
    for (int d = tid; d < DM; d += 256) {
        float y = x[base + d] + moe[base + d];
        ys[d] = y; s += y;
    }
    s = warp_sum(s);
    if (lane == 0) red[w] = s;
    __syncthreads();
    if (tid == 0) {
        float tt = 0;
        for (int i = 0; i < 8; i++) tt += red[i];
        red[8] = tt * (1.f / DM);
    }
    __syncthreads();
    const float mean = red[8];
    float vs = 0.f;
    for (int d = tid; d < DM; d += 256) { float c = ys[d] - mean; vs = fmaf(c, c, vs); }
    vs = warp_sum(vs);
    __syncthreads();
    if (lane == 0) red[w] = vs;
    __syncthreads();
    if (tid == 0) {
        float tt = 0;
        for (int i = 0; i < 8; i++) tt += red[i];
        red[8] = rsqrtf(tt * (1.f / DM) + 1e-5f);
    }
    __syncthreads();
    const float rstd = red[8];
    for (int d = tid; d < DM; d += 256)
        x[base + d] = (ys[d] - mean) * rstd * g[d] + b[d];
}

// ---------------- host orchestration ----------------
template <int EPI>
static void gemm(const float* A, const float* W, const float* bias, float* C,
                 int M, int N, int K,
                 const float* r0 = nullptr, const float* r1 = nullptr,
                 const float* sp = nullptr, const float* gate = nullptr,
                 float alpha = 1.f, int accum = 0) {
    GemmP p;
    p.A = A; p.W = W; p.bias = bias; p.C = C;
    p.M = M; p.N = N; p.K = K;
    p.r0 = r0; p.r1 = r1; p.scal = sp; p.gate = gate;
    p.alpha = alpha; p.accum = accum;
    dim3 grid(N / 128, M / 128);
    gemm_nt<EPI><<<grid, 256>>>(p);
}

extern "C" void kernel_launch(void* const* d_in, const int* in_sizes, int n_in,
                              void* d_out, int out_size) {
    (void)in_sizes; (void)n_in; (void)out_size;
    const int*   src    = (const int*)  d_in[0];
    const float* qstate = (const float*)d_in[1];
    const float* noise  = (const float*)d_in[2];
    const float* embW   = (const float*)d_in[3];
    const float* qprojW = (const float*)d_in[4];
    const float* qprojB = (const float*)d_in[5];
    const float* posW   = (const float*)d_in[6];
    const float* posB   = (const float*)d_in[7];
    const float* inW    = (const float*)d_in[8];
    const float* inB    = (const float*)d_in[9];
    const float* outW   = (const float*)d_in[10];
    const float* outB   = (const float*)d_in[11];
    const float* entW   = (const float*)d_in[12];
    const float* entB   = (const float*)d_in[13];
    const float* gateW  = (const float*)d_in[14];
    const float* gateB  = (const float*)d_in[15];
    const float* qgW    = (const float*)d_in[16];
    const float* qgB    = (const float*)d_in[17];
    const float* ew1    = (const float*)d_in[18];
    const float* eb1    = (const float*)d_in[19];
    const float* ew2    = (const float*)d_in[20];
    const float* eb2    = (const float*)d_in[21];
    const float* lnG    = (const float*)d_in[22];
    const float* lnB    = (const float*)d_in[23];
    const float* fcW    = (const float*)d_in[24];
    const float* fcB    = (const float*)d_in[25];
    float* out = (float*)d_out;

    float *emb, *x, *qkv, *att, *o, *o2, *hbuf, *moe, *gates;
    cudaGetSymbolAddress((void**)&emb,   g_emb);
    cudaGetSymbolAddress((void**)&x,     g_x);
    cudaGetSymbolAddress((void**)&qkv,   g_qkv);
    cudaGetSymbolAddress((void**)&att,   g_att);
    cudaGetSymbolAddress((void**)&o,     g_o);
    cudaGetSymbolAddress((void**)&o2,    g_o2);
    cudaGetSymbolAddress((void**)&hbuf,  g_h);
    cudaGetSymbolAddress((void**)&moe,   g_moe);
    cudaGetSymbolAddress((void**)&gates, g_gates);

    // embedding + quantum mix + positional encoder on noise
    gather_emb<<<TOK, 256>>>(src, embW, emb);
    gemm<EPI_QEMB>(emb, qprojW, qprojB, x, TOK, DM, DM, emb, nullptr, qstate);
    gemm<EPI_POS>(noise, posW, posB, x, TOK, DM, DM, x, nullptr, nullptr, nullptr, 0.01f);

    for (int l = 0; l < LL; l++) {
        // attention
        gemm<EPI_BIAS>(x, inW + (size_t)l * 3 * DM * DM, inB + (size_t)l * 3 * DM, qkv, TOK, 3 * DM, DM);
        attn_scores<<<dim3(SQ / 32, BB * HN), 256>>>(qkv, att, 0.125f);
        softmax512<<<BB * HN * SQ, 256>>>(att);
        attn_av<<<dim3(SQ / 32, BB * HN), 256>>>(qkv, att, o);
        gemm<EPI_BIAS>(o, outW + (size_t)l * DM * DM, outB + (size_t)l * DM, o2, TOK, DM, DM);
        // x = x + o2 + 0.1*(o2 @ ent^T + ent_b)
        gemm<EPI_ENT>(o2, entW + (size_t)l * DM * DM, entB + (size_t)l * DM, x, TOK, DM, DM, x, o2);

        // MoE routing + dense experts
        gate_kernel<<<TOK, 256>>>(x, gateW + (size_t)l * EE * DM, gateB + (size_t)l * EE,
                                  qgW + (size_t)l * EE * DM, qgB + (size_t)l * EE, gates);
        for (int e = 0; e < EE; e++) {
            const size_t ix = (size_t)l * EE + e;
            gemm<EPI_GELU>(x, ew1 + ix * FF * DM, eb1 + ix * FF, hbuf, TOK, FF, DM);
            gemm<EPI_MOE>(hbuf, ew2 + ix * (size_t)DM * FF, eb2 + ix * DM, moe, TOK, DM, FF,
                          nullptr, nullptr, nullptr, gates + e, 1.f, e > 0);
        }
        ln_add<<<TOK, 256>>>(x, moe, lnG + (size_t)l * DM, lnB + (size_t)l * DM);
    }

    // final projection to vocab
    gemm<EPI_BIAS>(x, fcW, fcB, out, TOK, VV, DM);
}